// round 3
// baseline (speedup 1.0000x reference)
#include <cuda_runtime.h>
#include <cstdint>

#define N_PRE   1024
#define N_POST  2048
#define SEQ_T   4096
#define DECAY   0.9f
#define V_TH    1.0f
#define MAXA    192            // max active pre per timestep (mean 102, sd 9.6; 192 ~ 9 sigma)

// ---------------- device scratch (no cudaMalloc allowed) --------------------------------
__device__ int   g_cnt[SEQ_T];                          // active count per timestep
__device__ int   g_idx[SEQ_T * MAXA];                   // active pre indices per timestep
__device__ float g_cur[(size_t)SEQ_T * N_POST];         // currents in [t][n] layout, 32 MB

// ---------------- kernel 1: build per-timestep active index lists ------------------------
__global__ void k_build_lists(const float* __restrict__ stim) {
    const int t = blockIdx.x * blockDim.x + threadIdx.x;
    if (t >= SEQ_T) return;
    int cnt = 0;
    int* lp = &g_idx[t * MAXA];
    for (int p = 0; p < N_PRE; p++) {
        if (stim[(size_t)p * SEQ_T + t] > 0.5f) {       // coalesced across threads
            if (cnt < MAXA) lp[cnt] = p;
            cnt++;
        }
    }
    g_cnt[t] = cnt < MAXA ? cnt : MAXA;
}

// ---------------- kernel 2: smem-staged sparse gather -----------------------------------
// grid (64 n-slices, 2 t-halves), block 256. Each block stages W[all p][32 n] in smem
// (transposed on the fly from W[n][p], pad 33 => conflict-free store AND load), then
// each warp owns one t at a time: 32 lanes = 32 n, sum over active p via LDS (1 row =
// 128 B/cyc, zero conflicts). Moves the 3.3 GB of W-row traffic off the L2 crossbar
// (~6.3 KB/cyc chip) onto smem (~19 KB/cyc chip).
#define GN 32
#define GPAD 33
__global__ void __launch_bounds__(256) k_gather(const float* __restrict__ W) {
    extern __shared__ float sw[];                       // [N_PRE][GPAD]
    const int n0 = blockIdx.x * GN;
    const int t0 = blockIdx.y * (SEQ_T / 2);

    // stage W slice: read W[n0+r][p] rows (coalesced float4), scatter transposed
    for (int idx = threadIdx.x; idx < GN * (N_PRE / 4); idx += 256) {
        const int r  = idx / (N_PRE / 4);
        const int p4 = idx % (N_PRE / 4);
        const float4 w = ((const float4*)(W + (size_t)(n0 + r) * N_PRE))[p4];
        sw[(4 * p4 + 0) * GPAD + r] = w.x;
        sw[(4 * p4 + 1) * GPAD + r] = w.y;
        sw[(4 * p4 + 2) * GPAD + r] = w.z;
        sw[(4 * p4 + 3) * GPAD + r] = w.w;
    }
    __syncthreads();

    const int warp = threadIdx.x >> 5;
    const int lane = threadIdx.x & 31;

    for (int t = t0 + warp; t < t0 + SEQ_T / 2; t += 8) {
        const int c = g_cnt[t];
        const int* __restrict__ lp = &g_idx[t * MAXA];
        float a0 = 0.f, a1 = 0.f, a2 = 0.f, a3 = 0.f;
        int j = 0;
        for (; j + 4 <= c; j += 4) {
            const int p0 = lp[j], p1 = lp[j + 1], p2 = lp[j + 2], p3 = lp[j + 3];
            a0 += sw[p0 * GPAD + lane];
            a1 += sw[p1 * GPAD + lane];
            a2 += sw[p2 * GPAD + lane];
            a3 += sw[p3 * GPAD + lane];
        }
        for (; j < c; j++) a0 += sw[lp[j] * GPAD + lane];
        g_cur[(size_t)t * N_POST + n0 + lane] = (a0 + a1) + (a2 + a3);
    }
}

// ---------------- kernel 3: LIF scan, spill-free static 3-stage pipeline -----------------
// One chain per thread, 64 blocks x 32 threads = 2048 chains. Buffer rotation is fully
// unrolled with a COMPILE-TIME stage index so every buf[][] access is a register (the R2
// version used buf[tile % 3] -> local-memory spill -> 249us). buf[s] is reloaded with
// tile+3 right after processing: its next consumer is 2 full stages (~380 cyc) away,
// covering L2 latency. Output rows are per-thread contiguous float4 stores.
#define TT 16
__global__ void __launch_bounds__(32) k_lif_scan(float* __restrict__ out) {
    const int n = blockIdx.x * 32 + threadIdx.x;
    float* __restrict__ out_s = out + (size_t)n * SEQ_T;
    float* __restrict__ out_v = out + (size_t)N_POST * SEQ_T + (size_t)n * SEQ_T;

    const int NT = SEQ_T / TT;                          // 256 tiles
    float buf[3][TT];

    // prime tiles 0..2 (all indices compile-time)
#pragma unroll
    for (int s = 0; s < 3; s++)
#pragma unroll
        for (int k = 0; k < TT; k++)
            buf[s][k] = g_cur[(size_t)(s * TT + k) * N_POST + n];

    float v = 0.f;
    for (int base = 0; base < NT; base += 3) {
#pragma unroll
        for (int s = 0; s < 3; s++) {
            const int tile = base + s;
            if (tile < NT) {
                // serial LIF chain on resident tile
                float sb[TT], vb[TT];
#pragma unroll
                for (int k = 0; k < TT; k++) {
                    v = v * DECAY + buf[s][k];
                    const bool f = (v >= V_TH);
                    sb[k] = f ? 1.f : 0.f;
                    v = f ? 0.f : v;
                    vb[k] = v;
                }
                // refill this buffer for tile+3 (consumed 2 stages later)
                if (tile + 3 < NT) {
#pragma unroll
                    for (int k = 0; k < TT; k++)
                        buf[s][k] = g_cur[(size_t)((tile + 3) * TT + k) * N_POST + n];
                }
                // vectorized contiguous row writes
                const size_t o4 = (size_t)tile * (TT / 4);
#pragma unroll
                for (int q = 0; q < TT / 4; q++) {
                    ((float4*)out_s)[o4 + q] =
                        make_float4(sb[4 * q], sb[4 * q + 1], sb[4 * q + 2], sb[4 * q + 3]);
                    ((float4*)out_v)[o4 + q] =
                        make_float4(vb[4 * q], vb[4 * q + 1], vb[4 * q + 2], vb[4 * q + 3]);
                }
            }
        }
    }
}

// ---------------- launch --------------------------------------------------------------
extern "C" void kernel_launch(void* const* d_in, const int* in_sizes, int n_in,
                              void* d_out, int out_size) {
    const float* stim = (const float*)d_in[0];   // [N_PRE, SEQ_T]
    const float* W    = (const float*)d_in[1];   // [N_POST, N_PRE]
    if (n_in >= 2 && in_sizes[0] == N_POST * N_PRE && in_sizes[1] == N_PRE * SEQ_T) {
        const float* tmp = stim; stim = W; W = tmp;
    }
    float* out = (float*)d_out;

    static int smem_set = 0;
    const int GATHER_SMEM = N_PRE * GPAD * (int)sizeof(float);   // 135,168 B
    if (!smem_set) {
        cudaFuncSetAttribute(k_gather, cudaFuncAttributeMaxDynamicSharedMemorySize, GATHER_SMEM);
        smem_set = 1;
    }

    k_build_lists<<<SEQ_T / 256, 256>>>(stim);
    k_gather<<<dim3(N_POST / GN, 2), 256, GATHER_SMEM>>>(W);
    k_lif_scan<<<N_POST / 32, 32>>>(out);
}

// round 4
// speedup vs baseline: 2.0794x; 2.0794x over previous
#include <cuda_runtime.h>
#include <cstdint>

#define N_PRE   1024
#define N_POST  2048
#define SEQ_T   4096
#define DECAY   0.9f
#define V_TH    1.0f
#define MAXA    192            // max active pre per timestep (mean 102, sd 9.6; 192 ~ 9 sigma)

// ---------------- device scratch (no cudaMalloc allowed) --------------------------------
__device__ float g_WT[N_PRE * (size_t)N_POST];          // W transposed: [p][n], 8 MB
__device__ int   g_cnt[SEQ_T];                          // active count per timestep
__device__ int   g_idx[SEQ_T * MAXA];                   // active pre indices per timestep
__device__ float g_cur[(size_t)SEQ_T * N_POST];         // currents in [t][n] layout, 32 MB

// ---------------- kernel 1: transpose W [n][p] -> WT [p][n] ------------------------------
__global__ void k_transpose(const float* __restrict__ W) {
    __shared__ float tile[32][33];
    const int p0 = blockIdx.x * 32;
    const int n0 = blockIdx.y * 32;
    const int tx = threadIdx.x, ty = threadIdx.y;   // block (32, 8)
#pragma unroll
    for (int i = 0; i < 32; i += 8)
        tile[ty + i][tx] = W[(size_t)(n0 + ty + i) * N_PRE + p0 + tx];
    __syncthreads();
#pragma unroll
    for (int i = 0; i < 32; i += 8)
        g_WT[(size_t)(p0 + ty + i) * N_POST + n0 + tx] = tile[tx][ty + i];
}

// ---------------- kernel 2: build per-timestep active index lists ------------------------
// One thread per t. 128 blocks x 32 threads -> covers ~128 SMs (the R2/R3 grid of 16
// blocks used only 16 SMs and cost ~127us). Loads are independent (coalesced across the
// warp at each p), the only serial dependence is the cnt counter (ALU).
__global__ void __launch_bounds__(32) k_build_lists(const float* __restrict__ stim) {
    const int t = blockIdx.x * 32 + threadIdx.x;
    int cnt = 0;
    int* lp = &g_idx[t * MAXA];
#pragma unroll 8
    for (int p = 0; p < N_PRE; p++) {
        if (stim[(size_t)p * SEQ_T + t] > 0.5f) {
            if (cnt < MAXA) lp[cnt] = p;
            cnt++;
        }
    }
    g_cnt[t] = cnt < MAXA ? cnt : MAXA;
}

// ---------------- kernel 3: sparse gather-accumulate: cur[t][n] = sum_{active p} WT[p][n]
// (R2 version — empirically the fast path: 8192 CTAs of pure float4 L2 reads give the
// LSU huge MLP; beats the 1-block/SM smem-staged variant from R3 by a wide margin.)
__global__ void __launch_bounds__(256) k_gather() {
    const int t  = blockIdx.x;
    const int n4 = blockIdx.y * 256 + threadIdx.x;          // float4 index into 2048 n
    const int c  = g_cnt[t];
    const int* __restrict__ lp = &g_idx[t * MAXA];

    float4 a0 = make_float4(0.f, 0.f, 0.f, 0.f);
    float4 a1 = make_float4(0.f, 0.f, 0.f, 0.f);
    float4 a2 = make_float4(0.f, 0.f, 0.f, 0.f);
    float4 a3 = make_float4(0.f, 0.f, 0.f, 0.f);

    int j = 0;
    for (; j + 4 <= c; j += 4) {
        const int p0 = lp[j], p1 = lp[j + 1], p2 = lp[j + 2], p3 = lp[j + 3];
        float4 w0 = ((const float4*)(g_WT + (size_t)p0 * N_POST))[n4];
        float4 w1 = ((const float4*)(g_WT + (size_t)p1 * N_POST))[n4];
        float4 w2 = ((const float4*)(g_WT + (size_t)p2 * N_POST))[n4];
        float4 w3 = ((const float4*)(g_WT + (size_t)p3 * N_POST))[n4];
        a0.x += w0.x; a0.y += w0.y; a0.z += w0.z; a0.w += w0.w;
        a1.x += w1.x; a1.y += w1.y; a1.z += w1.z; a1.w += w1.w;
        a2.x += w2.x; a2.y += w2.y; a2.z += w2.z; a2.w += w2.w;
        a3.x += w3.x; a3.y += w3.y; a3.z += w3.z; a3.w += w3.w;
    }
    for (; j < c; j++) {
        const int p0 = lp[j];
        float4 w0 = ((const float4*)(g_WT + (size_t)p0 * N_POST))[n4];
        a0.x += w0.x; a0.y += w0.y; a0.z += w0.z; a0.w += w0.w;
    }
    float4 s;
    s.x = (a0.x + a1.x) + (a2.x + a3.x);
    s.y = (a0.y + a1.y) + (a2.y + a3.y);
    s.z = (a0.z + a1.z) + (a2.z + a3.z);
    s.w = (a0.w + a1.w) + (a2.w + a3.w);
    ((float4*)(g_cur + (size_t)t * N_POST))[n4] = s;
}

// ---------------- kernel 4: LIF scan, spill-free static 3-stage pipeline -----------------
// One chain per thread, 64 blocks x 32 threads = 2048 chains across 64 SMs. Buffer
// rotation fully unrolled with COMPILE-TIME stage indices (register-resident; the R2
// dynamic-index version spilled to local). buf[s] is refilled for tile+3 right after
// processing, so its next consumer is 2 stages (~380 cyc of chain) away — covers L2.
#define TT 16
__global__ void __launch_bounds__(32) k_lif_scan(float* __restrict__ out) {
    const int n = blockIdx.x * 32 + threadIdx.x;
    float* __restrict__ out_s = out + (size_t)n * SEQ_T;
    float* __restrict__ out_v = out + (size_t)N_POST * SEQ_T + (size_t)n * SEQ_T;

    const int NT = SEQ_T / TT;                          // 256 tiles
    float buf[3][TT];

#pragma unroll
    for (int s = 0; s < 3; s++)
#pragma unroll
        for (int k = 0; k < TT; k++)
            buf[s][k] = g_cur[(size_t)(s * TT + k) * N_POST + n];

    float v = 0.f;
    for (int base = 0; base < NT; base += 3) {
#pragma unroll
        for (int s = 0; s < 3; s++) {
            const int tile = base + s;
            if (tile < NT) {
                float sb[TT], vb[TT];
#pragma unroll
                for (int k = 0; k < TT; k++) {
                    v = v * DECAY + buf[s][k];
                    const bool f = (v >= V_TH);
                    sb[k] = f ? 1.f : 0.f;
                    v = f ? 0.f : v;
                    vb[k] = v;
                }
                if (tile + 3 < NT) {
#pragma unroll
                    for (int k = 0; k < TT; k++)
                        buf[s][k] = g_cur[(size_t)((tile + 3) * TT + k) * N_POST + n];
                }
                const size_t o4 = (size_t)tile * (TT / 4);
#pragma unroll
                for (int q = 0; q < TT / 4; q++) {
                    ((float4*)out_s)[o4 + q] =
                        make_float4(sb[4 * q], sb[4 * q + 1], sb[4 * q + 2], sb[4 * q + 3]);
                    ((float4*)out_v)[o4 + q] =
                        make_float4(vb[4 * q], vb[4 * q + 1], vb[4 * q + 2], vb[4 * q + 3]);
                }
            }
        }
    }
}

// ---------------- launch --------------------------------------------------------------
extern "C" void kernel_launch(void* const* d_in, const int* in_sizes, int n_in,
                              void* d_out, int out_size) {
    const float* stim = (const float*)d_in[0];   // [N_PRE, SEQ_T]
    const float* W    = (const float*)d_in[1];   // [N_POST, N_PRE]
    if (n_in >= 2 && in_sizes[0] == N_POST * N_PRE && in_sizes[1] == N_PRE * SEQ_T) {
        const float* tmp = stim; stim = W; W = tmp;
    }
    float* out = (float*)d_out;

    k_transpose<<<dim3(N_PRE / 32, N_POST / 32), dim3(32, 8)>>>(W);
    k_build_lists<<<SEQ_T / 32, 32>>>(stim);
    k_gather<<<dim3(SEQ_T, N_POST / 1024), 256>>>();
    k_lif_scan<<<N_POST / 32, 32>>>(out);
}